// round 15
// baseline (speedup 1.0000x reference)
#include <cuda_runtime.h>
#include <cstdint>

#define T_STEPS 256
#define BATCH   128
#define DIN     1024
#define HID     1024
#define NGATE   4096  // 4*HID
#define NBLK    128

// Scratch (device globals; no allocation allowed in kernel_launch).
__device__ float g_G[(size_t)T_STEPS * BATCH * NGATE];   // x@Wx + b (512 MB)
__device__ float g_xA[(size_t)T_STEPS * BATCH * DIN];    // x, tf32-rounded, A-fragment order (128 MB)
__device__ float g_WxB[(size_t)DIN * NGATE];             // Wx, tf32-rounded, B-fragment order (16 MB)
__device__ float g_hF[2][BATCH * HID];                   // h (raw fp32), A-FRAGMENT order, dbl-buffered
__device__ float g_c[BATCH * HID];                       // cell state
__device__ unsigned g_cnt;                               // barrier arrive counter
__device__ volatile unsigned g_gen;                      // barrier generation

// ---------------- helpers ----------------

__device__ __forceinline__ float f2tf32(float x) {
    uint32_t u;
    asm("cvt.rna.tf32.f32 %0, %1;" : "=r"(u) : "f"(x));
    return __uint_as_float(u);
}

__device__ __forceinline__ void mma_tf32(float c[4], const uint32_t a[4], const uint32_t b[2]) {
    asm volatile(
        "mma.sync.aligned.m16n8k8.row.col.f32.tf32.tf32.f32 "
        "{%0,%1,%2,%3}, {%4,%5,%6,%7}, {%8,%9}, {%0,%1,%2,%3};"
        : "+f"(c[0]), "+f"(c[1]), "+f"(c[2]), "+f"(c[3])
        : "r"(a[0]), "r"(a[1]), "r"(a[2]), "r"(a[3]), "r"(b[0]), "r"(b[1]));
}

__device__ __forceinline__ float sigmoidf_fast(float x) {
    x = fminf(fmaxf(x, -30.f), 30.f);
    return __fdividef(1.f, 1.f + __expf(-x));
}

__device__ __forceinline__ float tanhf_fast(float x) {
    x = fminf(fmaxf(x, -15.f), 15.f);
    float e = __expf(2.f * x);
    return __fdividef(e - 1.f, e + 1.f);
}

// Software grid barrier (R9-proven atomic-counter version).
__device__ __forceinline__ void grid_sync(unsigned step) {
    __syncthreads();
    if (threadIdx.x == 0) {
        __threadfence();
        unsigned a = atomicAdd(&g_cnt, 1u);
        if (a == gridDim.x - 1) {
            g_cnt = 0;
            __threadfence();
            g_gen = step + 1;
        } else {
            while (g_gen < step + 1) __nanosleep(32);
        }
        __threadfence();
    }
    __syncthreads();
}

// ---------------- init state + barrier ----------------
// Fragment index for h[row][k]:
//   warp=row/16, g=row%8, r=(row%16)/8, kb8=k/8, t4=k%4, s=(k%8)/4
//   float idx = ((warp*128 + kb8)*32 + g*4 + t4)*4 + (r + 2*s)

__global__ void init_state(const float* __restrict__ csh) {
    int idx = blockIdx.x * blockDim.x + threadIdx.x;
    if (idx == 0) { g_cnt = 0; g_gen = 0; }
    if (idx < BATCH * HID) {
        int row = idx / HID, k = idx % HID;
        g_c[idx] = csh[row * 2 * HID + k];                 // cell first
        float h0 = csh[row * 2 * HID + HID + k];           // hidden second
        int warp = row >> 4, g = row & 7, r = (row >> 3) & 1;
        int kb8 = k >> 3, t4 = k & 3, s = (k >> 2) & 1;
        g_hF[0][((warp * 128 + kb8) * 32 + g * 4 + t4) * 4 + r + 2 * s] = h0;
    }
}

// ---------------- prep: permute+round x and Wx into fragment tile order ----

__global__ void prep_xA(const float* __restrict__ x) {
    __shared__ float tl[128 * 33];
    int ki = blockIdx.x, mi = blockIdx.y;
    int tid = threadIdx.x;  // 256
    for (int i = 0; i < 16; i++) {
        int e = tid + i * 256, r = e >> 5, c = e & 31;
        tl[r * 33 + c] = x[(size_t)(mi * 128 + r) * DIN + ki * 32 + c];
    }
    __syncthreads();
    size_t base = ((size_t)mi * 32 + ki) << 12;  // *4096
    for (int i = 0; i < 4; i++) {
        int o = tid + i * 256;           // float4 index 0..1023
        int lane = o & 31, mt = (o >> 5) & 1, wm = (o >> 6) & 3, k8 = o >> 8;
        int g = lane >> 2, t4 = lane & 3;
        int r0 = wm * 32 + mt * 16 + g, r1 = r0 + 8;
        int ka = k8 * 8 + t4, kb = ka + 4;
        float4 v;
        v.x = f2tf32(tl[r0 * 33 + ka]);
        v.y = f2tf32(tl[r1 * 33 + ka]);
        v.z = f2tf32(tl[r0 * 33 + kb]);
        v.w = f2tf32(tl[r1 * 33 + kb]);
        ((float4*)(g_xA + base))[o] = v;
    }
}

__global__ void prep_WxB(const float* __restrict__ Wx) {
    __shared__ float tl[32 * 129];
    int ni = blockIdx.x, ki = blockIdx.y;
    int tid = threadIdx.x;  // 256
    for (int i = 0; i < 16; i++) {
        int e = tid + i * 256, r = e >> 7, c = e & 127;
        tl[r * 129 + c] = Wx[(size_t)(ki * 32 + r) * NGATE + ni * 128 + c];
    }
    __syncthreads();
    size_t base = ((size_t)ki * 32 + ni) << 12;
    for (int i = 0; i < 4; i++) {
        int o = tid + i * 256;
        int lane = o & 31, w = (o >> 5) & 3, wn = (o >> 7) & 1, k8 = o >> 8;
        int g = lane >> 2, t4 = lane & 3;
        int c0 = wn * 64 + (2 * w) * 8 + g, c1 = c0 + 8;
        int ka = k8 * 8 + t4, kb = ka + 4;
        float4 v;
        v.x = f2tf32(tl[ka * 129 + c0]);
        v.y = f2tf32(tl[kb * 129 + c0]);
        v.z = f2tf32(tl[ka * 129 + c1]);
        v.w = f2tf32(tl[kb * 129 + c1]);
        ((float4*)(g_WxB + base))[o] = v;
    }
}

// ---------------- pre-GEMM: G = x @ Wx + bias ----------------
// Direct fragment streaming (R14 best-passing, verbatim).

__global__ __launch_bounds__(256) void pregemm(const float* __restrict__ bias) {
    const int tid  = threadIdx.x;
    const int warp = tid >> 5, lane = tid & 31;
    const int g  = lane >> 2, t4 = lane & 3;
    const int wm = warp >> 1, wn = warp & 1;
    const int ni = blockIdx.x, mi = blockIdx.y;
    const int m0 = mi * 128, n0 = ni * 128;

    const float4* ApL = (const float4*)g_xA + ((size_t)mi << 15) + wm * 64 + lane;
    const float4* BpL = (const float4*)g_WxB + ((size_t)ni << 10) + wn * 128 + lane;

    float acc[2][8][4];
#pragma unroll
    for (int a = 0; a < 2; a++)
#pragma unroll
        for (int b = 0; b < 8; b++)
#pragma unroll
            for (int c = 0; c < 4; c++) acc[a][b][c] = 0.f;

    float4 abuf[2][2], bbuf[2][4];
    abuf[0][0] = __ldg(ApL);
    abuf[0][1] = __ldg(ApL + 32);
#pragma unroll
    for (int w = 0; w < 4; w++) bbuf[0][w] = __ldg(BpL + w * 32);

#pragma unroll 2
    for (int kk = 0; kk < 128; kk++) {
        const int cur = kk & 1, nxt = cur ^ 1;
        if (kk < 127) {
            const int k2 = kk + 1;
            const float4* ap = ApL + (size_t)k2 * 256;
            abuf[nxt][0] = __ldg(ap);
            abuf[nxt][1] = __ldg(ap + 32);
            const float4* bp = BpL + ((size_t)(k2 >> 2) << 15) + (k2 & 3) * 256;
#pragma unroll
            for (int w = 0; w < 4; w++) bbuf[nxt][w] = __ldg(bp + w * 32);
        }
        uint32_t a0[4] = {__float_as_uint(abuf[cur][0].x), __float_as_uint(abuf[cur][0].y),
                          __float_as_uint(abuf[cur][0].z), __float_as_uint(abuf[cur][0].w)};
        uint32_t a1[4] = {__float_as_uint(abuf[cur][1].x), __float_as_uint(abuf[cur][1].y),
                          __float_as_uint(abuf[cur][1].z), __float_as_uint(abuf[cur][1].w)};
#pragma unroll
        for (int w = 0; w < 4; w++) {
            float4 fb = bbuf[cur][w];
            uint32_t b0[2] = {__float_as_uint(fb.x), __float_as_uint(fb.y)};
            uint32_t b1[2] = {__float_as_uint(fb.z), __float_as_uint(fb.w)};
            mma_tf32(acc[0][2 * w],     a0, b0);
            mma_tf32(acc[1][2 * w],     a1, b0);
            mma_tf32(acc[0][2 * w + 1], a0, b1);
            mma_tf32(acc[1][2 * w + 1], a1, b1);
        }
    }

#pragma unroll
    for (int mt = 0; mt < 2; mt++) {
#pragma unroll
        for (int nt = 0; nt < 8; nt++) {
            int r = m0 + wm * 32 + mt * 16 + g;
            int c = n0 + wn * 64 + nt * 8 + 2 * t4;
            float b0 = bias[c], b1 = bias[c + 1];
            float2 v0 = make_float2(acc[mt][nt][0] + b0, acc[mt][nt][1] + b1);
            float2 v1 = make_float2(acc[mt][nt][2] + b0, acc[mt][nt][3] + b1);
            *(float2*)&g_G[(size_t)r * NGATE + c]       = v0;
            *(float2*)&g_G[(size_t)(r + 8) * NGATE + c] = v1;
        }
    }
}

// ---------------- persistent recurrence ----------------
// R14 structure; single change: B-fragment LDS double-buffered one kb8 ahead
// so LDS latency overlaps the current iteration's mma group.

#define BFRAG_FLOATS 32768       // 128 kblocks * 256 (Wh, resident)
#define LS_SMEM_BYTES (BFRAG_FLOATS * 4)  // 128 KB
#define RING 16

__global__ __launch_bounds__(256, 1) void lstm_persistent(
        const float* __restrict__ mask,
        const float* __restrict__ Wh,
        float* __restrict__ out_hs) {
    extern __shared__ float smem[];
    float* Bfrag = smem;

    const int tid  = threadIdx.x;
    const int warp = tid >> 5, lane = tid & 31;
    const int g  = lane >> 2, t4 = lane & 3;
    const int bx = blockIdx.x;
    const int j0 = bx * 8;
    const int rb = warp * 16;
    const int colb = j0 + 2 * t4;

    // epilogue fragment-store offsets (within this warp's kb8=bx tile)
    const int krel0 = 2 * t4, krel1 = 2 * t4 + 1;
    const int off0 = (g * 4 + (krel0 & 3)) * 4 + 2 * ((krel0 >> 2) & 1);
    const int off1 = (g * 4 + (krel1 & 3)) * 4 + 2 * ((krel1 >> 2) & 1);

    // ---- preload Wh fragments (once per launch) ----
    for (int idx = tid; idx < BFRAG_FLOATS; idx += 256) {
        int kb     = idx >> 8;
        int within = idx & 255;
        int q      = within >> 7;
        int rest   = within & 127;
        int lane_i = rest >> 2;
        int sub    = rest & 3;
        int gate   = q * 2 + (sub >> 1);
        int s      = sub & 1;
        int g8     = lane_i >> 2;
        int t4v    = lane_i & 3;
        int k      = kb * 8 + s * 4 + t4v;
        Bfrag[idx] = f2tf32(Wh[(size_t)k * NGATE + gate * HID + j0 + g8]);
    }
    __syncthreads();

    // per-step scalars for step 0
    float em0, em1;
    float2 pG[4][2];
    {
        em0 = 1.0f - __ldg(&mask[rb + g]);
        em1 = 1.0f - __ldg(&mask[rb + g + 8]);
#pragma unroll
        for (int r = 0; r < 2; r++) {
            size_t gb = ((size_t)(rb + g + r * 8)) * NGATE + colb;
#pragma unroll
            for (int gate = 0; gate < 4; gate++)
                pG[gate][r] = __ldg((const float2*)&g_G[gb + gate * HID]);
        }
    }

    for (int t = 0; t < T_STEPS; t++) {
        const float* __restrict__ hF_in = g_hF[t & 1] + (size_t)warp * 16384;
        float*       __restrict__ hF_out = g_hF[(t + 1) & 1];

        float nem0 = 0.f, nem1 = 0.f;
        float2 nG[4][2];
#pragma unroll
        for (int gate = 0; gate < 4; gate++) {
            nG[gate][0] = make_float2(0.f, 0.f);
            nG[gate][1] = make_float2(0.f, 0.f);
        }

        float acc[4][4];
#pragma unroll
        for (int a = 0; a < 4; a++)
#pragma unroll
            for (int c = 0; c < 4; c++) acc[a][c] = 0.f;

        // ring prologue: 16 outstanding coalesced LDG.128
        float4 ring[RING];
#pragma unroll
        for (int p = 0; p < RING; p++)
            ring[p] = *(const float4*)&hF_in[p * 128 + lane * 4];

        // B double-buffer prologue (kb8 = 0)
        float4 bAc = *(const float4*)&Bfrag[lane * 4];
        float4 bBc = *(const float4*)&Bfrag[128 + lane * 4];

#pragma unroll 16
        for (int kb8 = 0; kb8 < 128; kb8++) {
            float4 av = ring[kb8 & (RING - 1)];
            if (kb8 < 128 - RING)
                ring[kb8 & (RING - 1)] =
                    *(const float4*)&hF_in[(kb8 + RING) * 128 + lane * 4];

            // prefetch next kb8's B fragments (overlaps this iteration's mma)
            float4 bAn, bBn;
            if (kb8 < 127) {
                const float* Bn = Bfrag + (kb8 + 1) * 256;
                bAn = *(const float4*)&Bn[lane * 4];
                bBn = *(const float4*)&Bn[128 + lane * 4];
            }

            if (kb8 == 64 && t + 1 < T_STEPS) {
                const float* nmrow = mask + (size_t)(t + 1) * BATCH;
                nem0 = 1.0f - __ldg(&nmrow[rb + g]);
                nem1 = 1.0f - __ldg(&nmrow[rb + g + 8]);
#pragma unroll
                for (int r = 0; r < 2; r++) {
                    size_t gb = ((size_t)(t + 1) * BATCH + rb + g + r * 8) * NGATE + colb;
#pragma unroll
                    for (int gate = 0; gate < 4; gate++)
                        nG[gate][r] = __ldg((const float2*)&g_G[gb + gate * HID]);
                }
            }

            uint32_t afr[4];
            afr[0] = __float_as_uint(f2tf32(av.x * em0));
            afr[1] = __float_as_uint(f2tf32(av.y * em1));
            afr[2] = __float_as_uint(f2tf32(av.z * em0));
            afr[3] = __float_as_uint(f2tf32(av.w * em1));

            uint32_t b0[2] = {__float_as_uint(bAc.x), __float_as_uint(bAc.y)};
            uint32_t b1[2] = {__float_as_uint(bAc.z), __float_as_uint(bAc.w)};
            uint32_t b2[2] = {__float_as_uint(bBc.x), __float_as_uint(bBc.y)};
            uint32_t b3[2] = {__float_as_uint(bBc.z), __float_as_uint(bBc.w)};
            mma_tf32(acc[0], afr, b0);
            mma_tf32(acc[1], afr, b1);
            mma_tf32(acc[2], afr, b2);
            mma_tf32(acc[3], afr, b3);

            if (kb8 < 127) { bAc = bAn; bBc = bBn; }
        }

        // epilogue: LSTM pointwise + state/output/frag writes
        float* fb = hF_out + ((size_t)warp * 128 + bx) * 128;
#pragma unroll
        for (int r = 0; r < 2; r++) {
            int row = rb + g + r * 8;
            float em = r ? em1 : em0;
            float2 cp = *(const float2*)&g_c[row * HID + colb];
            float iv0 = acc[0][2 * r]     + pG[0][r].x;
            float iv1 = acc[0][2 * r + 1] + pG[0][r].y;
            float fv0 = acc[1][2 * r]     + pG[1][r].x;
            float fv1 = acc[1][2 * r + 1] + pG[1][r].y;
            float ov0 = acc[2][2 * r]     + pG[2][r].x;
            float ov1 = acc[2][2 * r + 1] + pG[2][r].y;
            float gv0 = acc[3][2 * r]     + pG[3][r].x;
            float gv1 = acc[3][2 * r + 1] + pG[3][r].y;
            float cn0 = sigmoidf_fast(fv0) * (cp.x * em) + sigmoidf_fast(iv0) * tanhf_fast(gv0);
            float cn1 = sigmoidf_fast(fv1) * (cp.y * em) + sigmoidf_fast(iv1) * tanhf_fast(gv1);
            float hn0 = sigmoidf_fast(ov0) * tanhf_fast(cn0);
            float hn1 = sigmoidf_fast(ov1) * tanhf_fast(cn1);
            *(float2*)&g_c[row * HID + colb] = make_float2(cn0, cn1);
            *(float2*)&out_hs[((size_t)t * BATCH + row) * HID + colb] = make_float2(hn0, hn1);
            fb[off0 + r] = hn0;   // raw h into next-step fragment buffer
            fb[off1 + r] = hn1;
        }

        grid_sync((unsigned)t);

        em0 = nem0; em1 = nem1;
#pragma unroll
        for (int gate = 0; gate < 4; gate++) {
            pG[gate][0] = nG[gate][0];
            pG[gate][1] = nG[gate][1];
        }
    }
}

// ---------------- final state writeback ----------------
// c from g_c; final hidden = hs[T-1] (already in out).

__global__ void write_final(float* __restrict__ out) {
    int idx = blockIdx.x * blockDim.x + threadIdx.x;
    if (idx < BATCH * HID) {
        int b = idx / HID, j = idx % HID;
        size_t base = (size_t)T_STEPS * BATCH * HID;
        out[base + (size_t)b * 2 * HID + j] = g_c[idx];
        out[base + (size_t)b * 2 * HID + HID + j] =
            out[(size_t)(T_STEPS - 1) * BATCH * HID + (size_t)b * HID + j];
    }
}

// ---------------- launch ----------------

extern "C" void kernel_launch(void* const* d_in, const int* in_sizes, int n_in,
                              void* d_out, int out_size) {
    const float* x    = (const float*)d_in[0];  // [T,B,D]
    const float* mask = (const float*)d_in[1];  // [T,B,1]
    const float* csh  = (const float*)d_in[2];  // [B,2H]
    const float* Wx   = (const float*)d_in[3];  // [D,4H]
    const float* Wh   = (const float*)d_in[4];  // [H,4H]
    const float* bias = (const float*)d_in[5];  // [4H]
    float* out = (float*)d_out;

    cudaFuncSetAttribute(lstm_persistent,
                         cudaFuncAttributeMaxDynamicSharedMemorySize, LS_SMEM_BYTES);

    init_state<<<(BATCH * HID + 255) / 256, 256>>>(csh);

    prep_xA<<<dim3(DIN / 32, (T_STEPS * BATCH) / 128), 256>>>(x);
    prep_WxB<<<dim3(NGATE / 128, DIN / 32), 256>>>(Wx);

    pregemm<<<dim3(NGATE / 128, (T_STEPS * BATCH) / 128), 256>>>(bias);

    lstm_persistent<<<NBLK, 256, LS_SMEM_BYTES>>>(mask, Wh, out);

    write_final<<<(BATCH * HID + 255) / 256, 256>>>(out);
}

// round 16
// speedup vs baseline: 1.1138x; 1.1138x over previous
#include <cuda_runtime.h>
#include <cstdint>

#define T_STEPS 256
#define BATCH   128
#define DIN     1024
#define HID     1024
#define NGATE   4096  // 4*HID
#define NBLK    128

// Scratch (device globals; no allocation allowed in kernel_launch).
__device__ float g_G[(size_t)T_STEPS * BATCH * NGATE];   // x@Wx + b (512 MB)
__device__ float g_xA[(size_t)T_STEPS * BATCH * DIN];    // x, tf32-rounded, A-fragment order (128 MB)
__device__ float g_WxB[(size_t)DIN * NGATE];             // Wx, tf32-rounded, B-fragment order (16 MB)
__device__ float g_hF[2][BATCH * HID];                   // h PRE-MASKED+tf32-rounded, A-frag order
__device__ float g_c[BATCH * HID];                       // cell state
__device__ unsigned g_cnt;                               // barrier arrive counter
__device__ volatile unsigned g_gen;                      // barrier generation

// ---------------- helpers ----------------

__device__ __forceinline__ float f2tf32(float x) {
    uint32_t u;
    asm("cvt.rna.tf32.f32 %0, %1;" : "=r"(u) : "f"(x));
    return __uint_as_float(u);
}

__device__ __forceinline__ void mma_tf32(float c[4], const uint32_t a[4], const uint32_t b[2]) {
    asm volatile(
        "mma.sync.aligned.m16n8k8.row.col.f32.tf32.tf32.f32 "
        "{%0,%1,%2,%3}, {%4,%5,%6,%7}, {%8,%9}, {%0,%1,%2,%3};"
        : "+f"(c[0]), "+f"(c[1]), "+f"(c[2]), "+f"(c[3])
        : "r"(a[0]), "r"(a[1]), "r"(a[2]), "r"(a[3]), "r"(b[0]), "r"(b[1]));
}

__device__ __forceinline__ float sigmoidf_fast(float x) {
    x = fminf(fmaxf(x, -30.f), 30.f);
    return __fdividef(1.f, 1.f + __expf(-x));
}

__device__ __forceinline__ float tanhf_fast(float x) {
    x = fminf(fmaxf(x, -15.f), 15.f);
    float e = __expf(2.f * x);
    return __fdividef(e - 1.f, e + 1.f);
}

// Software grid barrier (R9-proven atomic-counter version).
__device__ __forceinline__ void grid_sync(unsigned step) {
    __syncthreads();
    if (threadIdx.x == 0) {
        __threadfence();
        unsigned a = atomicAdd(&g_cnt, 1u);
        if (a == gridDim.x - 1) {
            g_cnt = 0;
            __threadfence();
            g_gen = step + 1;
        } else {
            while (g_gen < step + 1) __nanosleep(32);
        }
        __threadfence();
    }
    __syncthreads();
}

// ---------------- init state + barrier ----------------
// Fragment index for h[row][k]:
//   warp=row/16, g=row%8, r=(row%16)/8, kb8=k/8, t4=k%4, s=(k%8)/4
//   float idx = ((warp*128 + kb8)*32 + g*4 + t4)*4 + (r + 2*s)
// hF stores f2tf32(h * (1-mask)) — mask of the step that will CONSUME it.

__global__ void init_state(const float* __restrict__ csh,
                           const float* __restrict__ mask) {
    int idx = blockIdx.x * blockDim.x + threadIdx.x;
    if (idx == 0) { g_cnt = 0; g_gen = 0; }
    if (idx < BATCH * HID) {
        int row = idx / HID, k = idx % HID;
        g_c[idx] = csh[row * 2 * HID + k];                 // cell first
        float h0 = csh[row * 2 * HID + HID + k];           // hidden second
        float em = 1.0f - mask[row];                       // mask[0][row]
        int warp = row >> 4, g = row & 7, r = (row >> 3) & 1;
        int kb8 = k >> 3, t4 = k & 3, s = (k >> 2) & 1;
        g_hF[0][((warp * 128 + kb8) * 32 + g * 4 + t4) * 4 + r + 2 * s] = f2tf32(h0 * em);
    }
}

// ---------------- prep: permute+round x and Wx into fragment tile order ----

__global__ void prep_xA(const float* __restrict__ x) {
    __shared__ float tl[128 * 33];
    int ki = blockIdx.x, mi = blockIdx.y;
    int tid = threadIdx.x;  // 256
    for (int i = 0; i < 16; i++) {
        int e = tid + i * 256, r = e >> 5, c = e & 31;
        tl[r * 33 + c] = x[(size_t)(mi * 128 + r) * DIN + ki * 32 + c];
    }
    __syncthreads();
    size_t base = ((size_t)mi * 32 + ki) << 12;  // *4096
    for (int i = 0; i < 4; i++) {
        int o = tid + i * 256;           // float4 index 0..1023
        int lane = o & 31, mt = (o >> 5) & 1, wm = (o >> 6) & 3, k8 = o >> 8;
        int g = lane >> 2, t4 = lane & 3;
        int r0 = wm * 32 + mt * 16 + g, r1 = r0 + 8;
        int ka = k8 * 8 + t4, kb = ka + 4;
        float4 v;
        v.x = f2tf32(tl[r0 * 33 + ka]);
        v.y = f2tf32(tl[r1 * 33 + ka]);
        v.z = f2tf32(tl[r0 * 33 + kb]);
        v.w = f2tf32(tl[r1 * 33 + kb]);
        ((float4*)(g_xA + base))[o] = v;
    }
}

__global__ void prep_WxB(const float* __restrict__ Wx) {
    __shared__ float tl[32 * 129];
    int ni = blockIdx.x, ki = blockIdx.y;
    int tid = threadIdx.x;  // 256
    for (int i = 0; i < 16; i++) {
        int e = tid + i * 256, r = e >> 7, c = e & 127;
        tl[r * 129 + c] = Wx[(size_t)(ki * 32 + r) * NGATE + ni * 128 + c];
    }
    __syncthreads();
    size_t base = ((size_t)ki * 32 + ni) << 12;
    for (int i = 0; i < 4; i++) {
        int o = tid + i * 256;
        int lane = o & 31, w = (o >> 5) & 3, wn = (o >> 7) & 1, k8 = o >> 8;
        int g = lane >> 2, t4 = lane & 3;
        int c0 = wn * 64 + (2 * w) * 8 + g, c1 = c0 + 8;
        int ka = k8 * 8 + t4, kb = ka + 4;
        float4 v;
        v.x = f2tf32(tl[ka * 129 + c0]);
        v.y = f2tf32(tl[kb * 129 + c0]);
        v.z = f2tf32(tl[ka * 129 + c1]);
        v.w = f2tf32(tl[kb * 129 + c1]);
        ((float4*)(g_WxB + base))[o] = v;
    }
}

// ---------------- pre-GEMM: G = x @ Wx + bias ----------------
// Direct fragment streaming (R14 best-passing, verbatim).

__global__ __launch_bounds__(256) void pregemm(const float* __restrict__ bias) {
    const int tid  = threadIdx.x;
    const int warp = tid >> 5, lane = tid & 31;
    const int g  = lane >> 2, t4 = lane & 3;
    const int wm = warp >> 1, wn = warp & 1;
    const int ni = blockIdx.x, mi = blockIdx.y;
    const int m0 = mi * 128, n0 = ni * 128;

    const float4* ApL = (const float4*)g_xA + ((size_t)mi << 15) + wm * 64 + lane;
    const float4* BpL = (const float4*)g_WxB + ((size_t)ni << 10) + wn * 128 + lane;

    float acc[2][8][4];
#pragma unroll
    for (int a = 0; a < 2; a++)
#pragma unroll
        for (int b = 0; b < 8; b++)
#pragma unroll
            for (int c = 0; c < 4; c++) acc[a][b][c] = 0.f;

    float4 abuf[2][2], bbuf[2][4];
    abuf[0][0] = __ldg(ApL);
    abuf[0][1] = __ldg(ApL + 32);
#pragma unroll
    for (int w = 0; w < 4; w++) bbuf[0][w] = __ldg(BpL + w * 32);

#pragma unroll 2
    for (int kk = 0; kk < 128; kk++) {
        const int cur = kk & 1, nxt = cur ^ 1;
        if (kk < 127) {
            const int k2 = kk + 1;
            const float4* ap = ApL + (size_t)k2 * 256;
            abuf[nxt][0] = __ldg(ap);
            abuf[nxt][1] = __ldg(ap + 32);
            const float4* bp = BpL + ((size_t)(k2 >> 2) << 15) + (k2 & 3) * 256;
#pragma unroll
            for (int w = 0; w < 4; w++) bbuf[nxt][w] = __ldg(bp + w * 32);
        }
        uint32_t a0[4] = {__float_as_uint(abuf[cur][0].x), __float_as_uint(abuf[cur][0].y),
                          __float_as_uint(abuf[cur][0].z), __float_as_uint(abuf[cur][0].w)};
        uint32_t a1[4] = {__float_as_uint(abuf[cur][1].x), __float_as_uint(abuf[cur][1].y),
                          __float_as_uint(abuf[cur][1].z), __float_as_uint(abuf[cur][1].w)};
#pragma unroll
        for (int w = 0; w < 4; w++) {
            float4 fb = bbuf[cur][w];
            uint32_t b0[2] = {__float_as_uint(fb.x), __float_as_uint(fb.y)};
            uint32_t b1[2] = {__float_as_uint(fb.z), __float_as_uint(fb.w)};
            mma_tf32(acc[0][2 * w],     a0, b0);
            mma_tf32(acc[1][2 * w],     a1, b0);
            mma_tf32(acc[0][2 * w + 1], a0, b1);
            mma_tf32(acc[1][2 * w + 1], a1, b1);
        }
    }

#pragma unroll
    for (int mt = 0; mt < 2; mt++) {
#pragma unroll
        for (int nt = 0; nt < 8; nt++) {
            int r = m0 + wm * 32 + mt * 16 + g;
            int c = n0 + wn * 64 + nt * 8 + 2 * t4;
            float b0 = bias[c], b1 = bias[c + 1];
            float2 v0 = make_float2(acc[mt][nt][0] + b0, acc[mt][nt][1] + b1);
            float2 v1 = make_float2(acc[mt][nt][2] + b0, acc[mt][nt][3] + b1);
            *(float2*)&g_G[(size_t)r * NGATE + c]       = v0;
            *(float2*)&g_G[(size_t)(r + 8) * NGATE + c] = v1;
        }
    }
}

// ---------------- persistent recurrence ----------------
// R14 structure; single change: hF holds PRE-MASKED, PRE-ROUNDED values
// (written with next step's mask in the epilogue), so the mainloop A-path
// is a pure bit-reinterpret — no fma ops between load and mma.

#define BFRAG_FLOATS 32768       // 128 kblocks * 256 (Wh, resident)
#define LS_SMEM_BYTES (BFRAG_FLOATS * 4)  // 128 KB
#define RING 16

__global__ __launch_bounds__(256, 1) void lstm_persistent(
        const float* __restrict__ mask,
        const float* __restrict__ Wh,
        float* __restrict__ out_hs) {
    extern __shared__ float smem[];
    float* Bfrag = smem;

    const int tid  = threadIdx.x;
    const int warp = tid >> 5, lane = tid & 31;
    const int g  = lane >> 2, t4 = lane & 3;
    const int bx = blockIdx.x;
    const int j0 = bx * 8;
    const int rb = warp * 16;
    const int colb = j0 + 2 * t4;

    // epilogue fragment-store offsets (within this warp's kb8=bx tile)
    const int krel0 = 2 * t4, krel1 = 2 * t4 + 1;
    const int off0 = (g * 4 + (krel0 & 3)) * 4 + 2 * ((krel0 >> 2) & 1);
    const int off1 = (g * 4 + (krel1 & 3)) * 4 + 2 * ((krel1 >> 2) & 1);

    // ---- preload Wh fragments (once per launch) ----
    for (int idx = tid; idx < BFRAG_FLOATS; idx += 256) {
        int kb     = idx >> 8;
        int within = idx & 255;
        int q      = within >> 7;
        int rest   = within & 127;
        int lane_i = rest >> 2;
        int sub    = rest & 3;
        int gate   = q * 2 + (sub >> 1);
        int s      = sub & 1;
        int g8     = lane_i >> 2;
        int t4v    = lane_i & 3;
        int k      = kb * 8 + s * 4 + t4v;
        Bfrag[idx] = f2tf32(Wh[(size_t)k * NGATE + gate * HID + j0 + g8]);
    }
    __syncthreads();

    // per-step scalars for step 0
    float em0, em1;
    float2 pG[4][2];
    {
        em0 = 1.0f - __ldg(&mask[rb + g]);
        em1 = 1.0f - __ldg(&mask[rb + g + 8]);
#pragma unroll
        for (int r = 0; r < 2; r++) {
            size_t gb = ((size_t)(rb + g + r * 8)) * NGATE + colb;
#pragma unroll
            for (int gate = 0; gate < 4; gate++)
                pG[gate][r] = __ldg((const float2*)&g_G[gb + gate * HID]);
        }
    }

    for (int t = 0; t < T_STEPS; t++) {
        const float* __restrict__ hF_in = g_hF[t & 1] + (size_t)warp * 16384;
        float*       __restrict__ hF_out = g_hF[(t + 1) & 1];

        float nem0 = 0.f, nem1 = 0.f;
        float2 nG[4][2];
#pragma unroll
        for (int gate = 0; gate < 4; gate++) {
            nG[gate][0] = make_float2(0.f, 0.f);
            nG[gate][1] = make_float2(0.f, 0.f);
        }

        float acc[4][4];
#pragma unroll
        for (int a = 0; a < 4; a++)
#pragma unroll
            for (int c = 0; c < 4; c++) acc[a][c] = 0.f;

        // ring prologue: 16 outstanding coalesced LDG.128
        float4 ring[RING];
#pragma unroll
        for (int p = 0; p < RING; p++)
            ring[p] = *(const float4*)&hF_in[p * 128 + lane * 4];

#pragma unroll 16
        for (int kb8 = 0; kb8 < 128; kb8++) {
            float4 av = ring[kb8 & (RING - 1)];
            if (kb8 < 128 - RING)
                ring[kb8 & (RING - 1)] =
                    *(const float4*)&hF_in[(kb8 + RING) * 128 + lane * 4];

            if (kb8 == 64 && t + 1 < T_STEPS) {
                const float* nmrow = mask + (size_t)(t + 1) * BATCH;
                nem0 = 1.0f - __ldg(&nmrow[rb + g]);
                nem1 = 1.0f - __ldg(&nmrow[rb + g + 8]);
#pragma unroll
                for (int r = 0; r < 2; r++) {
                    size_t gb = ((size_t)(t + 1) * BATCH + rb + g + r * 8) * NGATE + colb;
#pragma unroll
                    for (int gate = 0; gate < 4; gate++)
                        nG[gate][r] = __ldg((const float2*)&g_G[gb + gate * HID]);
                }
            }

            // A fragments: pre-masked, pre-rounded — pure reinterpret
            uint32_t afr[4];
            afr[0] = __float_as_uint(av.x);
            afr[1] = __float_as_uint(av.y);
            afr[2] = __float_as_uint(av.z);
            afr[3] = __float_as_uint(av.w);

            const float* Bb = Bfrag + kb8 * 256;
            float4 bA = *(const float4*)&Bb[lane * 4];        // gates 0,1
            float4 bB = *(const float4*)&Bb[128 + lane * 4];  // gates 2,3
            uint32_t b0[2] = {__float_as_uint(bA.x), __float_as_uint(bA.y)};
            uint32_t b1[2] = {__float_as_uint(bA.z), __float_as_uint(bA.w)};
            uint32_t b2[2] = {__float_as_uint(bB.x), __float_as_uint(bB.y)};
            uint32_t b3[2] = {__float_as_uint(bB.z), __float_as_uint(bB.w)};
            mma_tf32(acc[0], afr, b0);
            mma_tf32(acc[1], afr, b1);
            mma_tf32(acc[2], afr, b2);
            mma_tf32(acc[3], afr, b3);
        }

        // epilogue: LSTM pointwise + state/output/frag writes
        float* fb = hF_out + ((size_t)warp * 128 + bx) * 128;
#pragma unroll
        for (int r = 0; r < 2; r++) {
            int row = rb + g + r * 8;
            float em  = r ? em1 : em0;    // this step's mask (for c)
            float nem = r ? nem1 : nem0;  // next step's mask (for hF)
            float2 cp = *(const float2*)&g_c[row * HID + colb];
            float iv0 = acc[0][2 * r]     + pG[0][r].x;
            float iv1 = acc[0][2 * r + 1] + pG[0][r].y;
            float fv0 = acc[1][2 * r]     + pG[1][r].x;
            float fv1 = acc[1][2 * r + 1] + pG[1][r].y;
            float ov0 = acc[2][2 * r]     + pG[2][r].x;
            float ov1 = acc[2][2 * r + 1] + pG[2][r].y;
            float gv0 = acc[3][2 * r]     + pG[3][r].x;
            float gv1 = acc[3][2 * r + 1] + pG[3][r].y;
            float cn0 = sigmoidf_fast(fv0) * (cp.x * em) + sigmoidf_fast(iv0) * tanhf_fast(gv0);
            float cn1 = sigmoidf_fast(fv1) * (cp.y * em) + sigmoidf_fast(iv1) * tanhf_fast(gv1);
            float hn0 = sigmoidf_fast(ov0) * tanhf_fast(cn0);
            float hn1 = sigmoidf_fast(ov1) * tanhf_fast(cn1);
            *(float2*)&g_c[row * HID + colb] = make_float2(cn0, cn1);
            *(float2*)&out_hs[((size_t)t * BATCH + row) * HID + colb] = make_float2(hn0, hn1);
            fb[off0 + r] = f2tf32(hn0 * nem);   // pre-masked+rounded for step t+1
            fb[off1 + r] = f2tf32(hn1 * nem);
        }

        grid_sync((unsigned)t);

        em0 = nem0; em1 = nem1;
#pragma unroll
        for (int gate = 0; gate < 4; gate++) {
            pG[gate][0] = nG[gate][0];
            pG[gate][1] = nG[gate][1];
        }
    }
}

// ---------------- final state writeback ----------------
// c from g_c; final hidden = hs[T-1] (already in out).

__global__ void write_final(float* __restrict__ out) {
    int idx = blockIdx.x * blockDim.x + threadIdx.x;
    if (idx < BATCH * HID) {
        int b = idx / HID, j = idx % HID;
        size_t base = (size_t)T_STEPS * BATCH * HID;
        out[base + (size_t)b * 2 * HID + j] = g_c[idx];
        out[base + (size_t)b * 2 * HID + HID + j] =
            out[(size_t)(T_STEPS - 1) * BATCH * HID + (size_t)b * HID + j];
    }
}

// ---------------- launch ----------------

extern "C" void kernel_launch(void* const* d_in, const int* in_sizes, int n_in,
                              void* d_out, int out_size) {
    const float* x    = (const float*)d_in[0];  // [T,B,D]
    const float* mask = (const float*)d_in[1];  // [T,B,1]
    const float* csh  = (const float*)d_in[2];  // [B,2H]
    const float* Wx   = (const float*)d_in[3];  // [D,4H]
    const float* Wh   = (const float*)d_in[4];  // [H,4H]
    const float* bias = (const float*)d_in[5];  // [4H]
    float* out = (float*)d_out;

    cudaFuncSetAttribute(lstm_persistent,
                         cudaFuncAttributeMaxDynamicSharedMemorySize, LS_SMEM_BYTES);

    init_state<<<(BATCH * HID + 255) / 256, 256>>>(csh, mask);

    prep_xA<<<dim3(DIN / 32, (T_STEPS * BATCH) / 128), 256>>>(x);
    prep_WxB<<<dim3(NGATE / 128, DIN / 32), 256>>>(Wx);

    pregemm<<<dim3(NGATE / 128, (T_STEPS * BATCH) / 128), 256>>>(bias);

    lstm_persistent<<<NBLK, 256, LS_SMEM_BYTES>>>(mask, Wh, out);

    write_final<<<(BATCH * HID + 255) / 256, 256>>>(out);
}